// round 3
// baseline (speedup 1.0000x reference)
#include <cuda_runtime.h>

// FullyConnectedTensorProduct: B=2^20, MUL=8, DIM=32, 4 paths of 8x8x8.
// R3: weights read via uniform __ldg (coalescer dedupes broadcast -> 1 wavefront,
// L1-resident 8KB). Inputs/outputs transpose-staged through padded smem so all
// gmem traffic is coalesced and all LDS is conflict-free. E=2 elements/thread
// share every weight load. fma.rn.f32x2 packs adjacent w; out1 applied k-major
// so packed accumulators multiply packed a directly.

typedef unsigned long long u64;

#define ALPHA_F     0.08838834764831845f   /* 1/sqrt(128) */
#define INV_SQRT3_F 0.5773502691896258f
#define SPITCH 257                         /* padded row stride (floats) */

static __device__ __forceinline__ u64 pk2(float lo, float hi) {
    u64 r;
    asm("mov.b64 %0, {%1, %2};"
        : "=l"(r) : "r"(__float_as_uint(lo)), "r"(__float_as_uint(hi)));
    return r;
}
static __device__ __forceinline__ u64 dup2(float x) { return pk2(x, x); }
static __device__ __forceinline__ void upk2(u64 v, float& lo, float& hi) {
    unsigned l_, h_;
    asm("mov.b64 {%0, %1}, %2;" : "=r"(l_), "=r"(h_) : "l"(v));
    lo = __uint_as_float(l_);
    hi = __uint_as_float(h_);
}
static __device__ __forceinline__ u64 ffma2(u64 a, u64 b, u64 c) {
    u64 d;
    asm("fma.rn.f32x2 %0, %1, %2, %3;" : "=l"(d) : "l"(a), "l"(b), "l"(c));
    return d;
}

__global__ __launch_bounds__(128, 3)
void fctp_kernel(const float* __restrict__ x1,
                 const float* __restrict__ x2,
                 const float* __restrict__ wt,
                 float* __restrict__ out)
{
    extern __shared__ float st[];          // [64][SPITCH]: rows 0..31 x1*ALPHA, 32..63 x2
    const int tid = threadIdx.x;
    const size_t eBase = (size_t)blockIdx.x * 256;

    // ---------- stage inputs transposed (coalesced gmem, conflict-free STS) ----------
    {
        const float4* g1 = (const float4*)(x1 + eBase * 32);
        const float4* g2 = (const float4*)(x2 + eBase * 32);
#pragma unroll
        for (int c = 0; c < 16; c++) {
            int lin = tid + c * 128;       // float4 index in [0,2048)
            int e   = lin >> 3;
            int f   = (lin & 7) << 2;
            float4 a = g1[lin];
            st[(f+0)*SPITCH + e] = a.x * ALPHA_F;
            st[(f+1)*SPITCH + e] = a.y * ALPHA_F;
            st[(f+2)*SPITCH + e] = a.z * ALPHA_F;
            st[(f+3)*SPITCH + e] = a.w * ALPHA_F;
            float4 b = g2[lin];
            st[(32+f+0)*SPITCH + e] = b.x;
            st[(32+f+1)*SPITCH + e] = b.y;
            st[(32+f+2)*SPITCH + e] = b.z;
            st[(32+f+3)*SPITCH + e] = b.w;
        }
    }
    __syncthreads();

    const int e0 = tid, e1 = tid + 128;

    // pre-dup s1 (x1 rows 0..7, already *ALPHA)
    u64 s1d[2][8];
#pragma unroll
    for (int u = 0; u < 8; u++) {
        s1d[0][u] = dup2(st[u*SPITCH + e0]);
        s1d[1][u] = dup2(st[u*SPITCH + e1]);
    }

    u64 o0[2][4] = {};

    // ---------------- W0: out0[w] += s2[v] * (sum_u s1[u] W0[u,v,w]) ----------------
#pragma unroll
    for (int v = 0; v < 8; v++) {
        u64 a[2][4] = {};
#pragma unroll
        for (int u = 0; u < 8; u++) {
            const int off = u*64 + v*8;
            ulonglong2 q0 = __ldg((const ulonglong2*)(wt + off));
            ulonglong2 q1 = __ldg((const ulonglong2*)(wt + off + 4));
#pragma unroll
            for (int je = 0; je < 2; je++) {
                a[je][0] = ffma2(s1d[je][u], q0.x, a[je][0]);
                a[je][1] = ffma2(s1d[je][u], q0.y, a[je][1]);
                a[je][2] = ffma2(s1d[je][u], q1.x, a[je][2]);
                a[je][3] = ffma2(s1d[je][u], q1.y, a[je][3]);
            }
        }
        {
            u64 sv0 = dup2(st[(32+v)*SPITCH + e0]);
            u64 sv1 = dup2(st[(32+v)*SPITCH + e1]);
#pragma unroll
            for (int i = 0; i < 4; i++) {
                o0[0][i] = ffma2(sv0, a[0][i], o0[0][i]);
                o0[1][i] = ffma2(sv1, a[1][i], o0[1][i]);
            }
        }
    }

    // ---------------- W2: out1[w,k] += v2[v,k] * (sum_u s1[u] W2[u,v,w]) ----------------
    u64 o1[2][3][4] = {};
#pragma unroll
    for (int v = 0; v < 8; v++) {
        u64 a[2][4] = {};
#pragma unroll
        for (int u = 0; u < 8; u++) {
            const int off = 1024 + u*64 + v*8;
            ulonglong2 q0 = __ldg((const ulonglong2*)(wt + off));
            ulonglong2 q1 = __ldg((const ulonglong2*)(wt + off + 4));
#pragma unroll
            for (int je = 0; je < 2; je++) {
                a[je][0] = ffma2(s1d[je][u], q0.x, a[je][0]);
                a[je][1] = ffma2(s1d[je][u], q0.y, a[je][1]);
                a[je][2] = ffma2(s1d[je][u], q1.x, a[je][2]);
                a[je][3] = ffma2(s1d[je][u], q1.y, a[je][3]);
            }
        }
#pragma unroll
        for (int je = 0; je < 2; je++) {
            const int e = je ? e1 : e0;
#pragma unroll
            for (int k = 0; k < 3; k++) {
                u64 vk = dup2(st[(40 + v*3 + k)*SPITCH + e]);
#pragma unroll
                for (int wp = 0; wp < 4; wp++)
                    o1[je][k][wp] = ffma2(vk, a[je][wp], o1[je][k][wp]);
            }
        }
    }

    // ---------------- W3: out1[w,k] += v1[u,k] * (sum_v s2[v] W3[u,v,w]) ----------------
    {
        u64 s2d[2][8];
#pragma unroll
        for (int v = 0; v < 8; v++) {
            s2d[0][v] = dup2(st[(32+v)*SPITCH + e0]);
            s2d[1][v] = dup2(st[(32+v)*SPITCH + e1]);
        }
#pragma unroll
        for (int u = 0; u < 8; u++) {
            u64 a[2][4] = {};
#pragma unroll
            for (int v = 0; v < 8; v++) {
                const int off = 1536 + u*64 + v*8;
                ulonglong2 q0 = __ldg((const ulonglong2*)(wt + off));
                ulonglong2 q1 = __ldg((const ulonglong2*)(wt + off + 4));
#pragma unroll
                for (int je = 0; je < 2; je++) {
                    a[je][0] = ffma2(s2d[je][v], q0.x, a[je][0]);
                    a[je][1] = ffma2(s2d[je][v], q0.y, a[je][1]);
                    a[je][2] = ffma2(s2d[je][v], q1.x, a[je][2]);
                    a[je][3] = ffma2(s2d[je][v], q1.y, a[je][3]);
                }
            }
#pragma unroll
            for (int je = 0; je < 2; je++) {
                const int e = je ? e1 : e0;
#pragma unroll
                for (int k = 0; k < 3; k++) {
                    u64 vk = dup2(st[(8 + u*3 + k)*SPITCH + e]);   // v1 (has ALPHA)
#pragma unroll
                    for (int wp = 0; wp < 4; wp++)
                        o1[je][k][wp] = ffma2(vk, a[je][wp], o1[je][k][wp]);
                }
            }
        }
    }

    // ---------------- W1: out0[w] += INV_SQRT3*(v1[u].v2[v]) * W1[u,v,w] ----------------
#pragma unroll
    for (int vh = 0; vh < 2; vh++) {
        float v2l[2][4][3];
#pragma unroll
        for (int je = 0; je < 2; je++) {
            const int e = je ? e1 : e0;
#pragma unroll
            for (int vl = 0; vl < 4; vl++)
#pragma unroll
                for (int k = 0; k < 3; k++)
                    v2l[je][vl][k] = st[(40 + (vh*4+vl)*3 + k)*SPITCH + e];
        }
#pragma unroll
        for (int u = 0; u < 8; u++) {
            float v1u[2][3];
#pragma unroll
            for (int je = 0; je < 2; je++) {
                const int e = je ? e1 : e0;
#pragma unroll
                for (int k = 0; k < 3; k++)
                    v1u[je][k] = st[(8 + u*3 + k)*SPITCH + e] * INV_SQRT3_F;
            }
#pragma unroll
            for (int vl = 0; vl < 4; vl++) {
                const int v = vh*4 + vl;
                const int off = 512 + u*64 + v*8;
                ulonglong2 q0 = __ldg((const ulonglong2*)(wt + off));
                ulonglong2 q1 = __ldg((const ulonglong2*)(wt + off + 4));
#pragma unroll
                for (int je = 0; je < 2; je++) {
                    float p = v1u[je][0] * v2l[je][vl][0];
                    p = fmaf(v1u[je][1], v2l[je][vl][1], p);
                    p = fmaf(v1u[je][2], v2l[je][vl][2], p);
                    u64 pd = dup2(p);
                    o0[je][0] = ffma2(pd, q0.x, o0[je][0]);
                    o0[je][1] = ffma2(pd, q0.y, o0[je][1]);
                    o0[je][2] = ffma2(pd, q1.x, o0[je][2]);
                    o0[je][3] = ffma2(pd, q1.y, o0[je][3]);
                }
            }
        }
    }

    // ---------------- stage outputs transposed, then coalesced drain ----------------
    __syncthreads();   // all input reads done before overwriting st
#pragma unroll
    for (int je = 0; je < 2; je++) {
        const int e = je ? e1 : e0;
        float r[32];
        upk2(o0[je][0], r[0], r[1]); upk2(o0[je][1], r[2], r[3]);
        upk2(o0[je][2], r[4], r[5]); upk2(o0[je][3], r[6], r[7]);
#pragma unroll
        for (int k = 0; k < 3; k++)
#pragma unroll
            for (int wp = 0; wp < 4; wp++) {
                float lo, hi;
                upk2(o1[je][k][wp], lo, hi);
                r[8 + (2*wp)  *3 + k] = lo;
                r[8 + (2*wp+1)*3 + k] = hi;
            }
#pragma unroll
        for (int f = 0; f < 32; f++)
            st[f*SPITCH + e] = r[f];
    }
    __syncthreads();
    {
        float4* go = (float4*)(out + eBase * 32);
#pragma unroll
        for (int c = 0; c < 16; c++) {
            int lin = tid + c * 128;
            int e   = lin >> 3;
            int f   = (lin & 7) << 2;
            float4 t;
            t.x = st[(f+0)*SPITCH + e];
            t.y = st[(f+1)*SPITCH + e];
            t.z = st[(f+2)*SPITCH + e];
            t.w = st[(f+3)*SPITCH + e];
            go[lin] = t;
        }
    }
}

extern "C" void kernel_launch(void* const* d_in, const int* in_sizes, int n_in,
                              void* d_out, int out_size)
{
    const float* x1 = (const float*)d_in[0];
    const float* x2 = (const float*)d_in[1];
    const float* wt = (const float*)d_in[2];
    float* out = (float*)d_out;

    int nelem  = out_size / 32;              // 2^20
    int blocks = nelem / 256;                // 256 elements per block (E=2, 128 thr)
    size_t smem = 64 * SPITCH * sizeof(float);   // 65792 B

    static bool attr_set = false;
    if (!attr_set) {
        cudaFuncSetAttribute(fctp_kernel,
                             cudaFuncAttributeMaxDynamicSharedMemorySize,
                             (int)smem);
        attr_set = true;
    }
    fctp_kernel<<<blocks, 128, smem>>>(x1, x2, wt, out);
}

// round 4
// speedup vs baseline: 1.4439x; 1.4439x over previous
#include <cuda_runtime.h>

// FullyConnectedTensorProduct: B=2^20, MUL=8, DIM=32, 4 paths of 8x8x8.
// R4: weights in smem (LDS.128 broadcast, cheap issue + hoistable), E=2
// elements/thread so each weight load feeds two elements. Inputs and outputs
// staged through stride-65 padded smem (conflict-free both ways) so all gmem
// traffic is coalesced float4. fma.rn.f32x2 packs adjacent w indices.
// ALPHA folded into x1 at staging; INV_SQRT3 folded into path-1 weights.

typedef unsigned long long u64;

#define ALPHA_F     0.08838834764831845f   /* 1/sqrt(128) */
#define INV_SQRT3_F 0.5773502691896258f
#define EPITCH 65                          /* floats per element row in staging */

static __device__ __forceinline__ u64 pk2(float lo, float hi) {
    u64 r;
    asm("mov.b64 %0, {%1, %2};"
        : "=l"(r) : "r"(__float_as_uint(lo)), "r"(__float_as_uint(hi)));
    return r;
}
static __device__ __forceinline__ u64 dup2(float x) { return pk2(x, x); }
static __device__ __forceinline__ void upk2(u64 v, float& lo, float& hi) {
    unsigned l_, h_;
    asm("mov.b64 {%0, %1}, %2;" : "=r"(l_), "=r"(h_) : "l"(v));
    lo = __uint_as_float(l_);
    hi = __uint_as_float(h_);
}
static __device__ __forceinline__ u64 ffma2(u64 a, u64 b, u64 c) {
    u64 d;
    asm("fma.rn.f32x2 %0, %1, %2, %3;" : "=l"(d) : "l"(a), "l"(b), "l"(c));
    return d;
}

// a0/a1 += s0/s1 * W[0..7]  (8 weights = 4 packed pairs, one 32B region)
static __device__ __forceinline__ void wacc(const float* wp, u64 s0, u64 s1,
                                            u64 a0[4], u64 a1[4]) {
    ulonglong2 q0 = *(const ulonglong2*)wp;
    ulonglong2 q1 = *(const ulonglong2*)(wp + 4);
    a0[0] = ffma2(s0, q0.x, a0[0]);
    a1[0] = ffma2(s1, q0.x, a1[0]);
    a0[1] = ffma2(s0, q0.y, a0[1]);
    a1[1] = ffma2(s1, q0.y, a1[1]);
    a0[2] = ffma2(s0, q1.x, a0[2]);
    a1[2] = ffma2(s1, q1.x, a1[2]);
    a0[3] = ffma2(s0, q1.y, a0[3]);
    a1[3] = ffma2(s1, q1.y, a1[3]);
}

__global__ __launch_bounds__(128, 3)
void fctp_kernel(const float* __restrict__ x1,
                 const float* __restrict__ x2,
                 const float* __restrict__ wt,
                 float* __restrict__ out)
{
    extern __shared__ __align__(16) float smem[];
    float* ws = smem;              // 2048 floats: weights (path1 * INV_SQRT3)
    float* st = smem + 2048;       // 256 * EPITCH: per-element staging

    const int tid = threadIdx.x;
    const size_t eBase = (size_t)blockIdx.x * 256;

    // ---- stage weights (INV_SQRT3 folded into path 1) ----
#pragma unroll
    for (int c = 0; c < 16; c++) {
        int i = tid + c * 128;
        float s = ((i >> 9) == 1) ? INV_SQRT3_F : 1.0f;
        ws[i] = __ldg(wt + i) * s;
    }

    // ---- stage inputs: x1*ALPHA at [e*65 + 0..31], x2 at [e*65 + 32..63] ----
    {
        const float4* g1 = (const float4*)(x1 + eBase * 32);
        const float4* g2 = (const float4*)(x2 + eBase * 32);
#pragma unroll
        for (int c = 0; c < 16; c++) {
            int lin = tid + c * 128;          // float4 index in [0,2048)
            int e = lin >> 3, j = (lin & 7) << 2;
            float4 a = g1[lin];
            float* p = st + e * EPITCH + j;
            p[0] = a.x * ALPHA_F; p[1] = a.y * ALPHA_F;
            p[2] = a.z * ALPHA_F; p[3] = a.w * ALPHA_F;
            float4 b = g2[lin];
            float* q = st + e * EPITCH + 32 + j;
            q[0] = b.x; q[1] = b.y; q[2] = b.z; q[3] = b.w;
        }
    }
    __syncthreads();

    const float* S0 = st + tid * EPITCH;
    const float* S1 = st + (tid + 128) * EPITCH;

    u64 o0[2][4] = {};
    u64 o1[2][3][4] = {};

    // ======== phase A: W0 + W2 (both need s1-dups) ========
    {
        u64 s1d[2][8];
#pragma unroll
        for (int u = 0; u < 8; u++) {
            s1d[0][u] = dup2(S0[u]);
            s1d[1][u] = dup2(S1[u]);
        }

        // W0: out0[w] += s2[v] * (sum_u s1[u] * W0[u,v,w])
#pragma unroll
        for (int v = 0; v < 8; v++) {
            u64 a[2][4] = {};
#pragma unroll
            for (int u = 0; u < 8; u++)
                wacc(&ws[u * 64 + v * 8], s1d[0][u], s1d[1][u], a[0], a[1]);
            u64 t0 = dup2(S0[32 + v]);
            u64 t1 = dup2(S1[32 + v]);
#pragma unroll
            for (int i = 0; i < 4; i++) {
                o0[0][i] = ffma2(t0, a[0][i], o0[0][i]);
                o0[1][i] = ffma2(t1, a[1][i], o0[1][i]);
            }
        }

        // W2: out1[w,k] += v2[v,k] * (sum_u s1[u] * W2[u,v,w])
#pragma unroll
        for (int v = 0; v < 8; v++) {
            u64 a[2][4] = {};
#pragma unroll
            for (int u = 0; u < 8; u++)
                wacc(&ws[1024 + u * 64 + v * 8], s1d[0][u], s1d[1][u], a[0], a[1]);
#pragma unroll
            for (int k = 0; k < 3; k++) {
                u64 t0 = dup2(S0[40 + v * 3 + k]);
                u64 t1 = dup2(S1[40 + v * 3 + k]);
#pragma unroll
                for (int wp = 0; wp < 4; wp++) {
                    o1[0][k][wp] = ffma2(t0, a[0][wp], o1[0][k][wp]);
                    o1[1][k][wp] = ffma2(t1, a[1][wp], o1[1][k][wp]);
                }
            }
        }
    }

    // ======== phase B: W3 (needs s2-dups) ========
    {
        u64 s2d[2][8];
#pragma unroll
        for (int v = 0; v < 8; v++) {
            s2d[0][v] = dup2(S0[32 + v]);
            s2d[1][v] = dup2(S1[32 + v]);
        }
#pragma unroll
        for (int u = 0; u < 8; u++) {
            u64 a[2][4] = {};
#pragma unroll
            for (int v = 0; v < 8; v++)
                wacc(&ws[1536 + u * 64 + v * 8], s2d[0][v], s2d[1][v], a[0], a[1]);
#pragma unroll
            for (int k = 0; k < 3; k++) {
                u64 t0 = dup2(S0[8 + u * 3 + k]);
                u64 t1 = dup2(S1[8 + u * 3 + k]);
#pragma unroll
                for (int wp = 0; wp < 4; wp++) {
                    o1[0][k][wp] = ffma2(t0, a[0][wp], o1[0][k][wp]);
                    o1[1][k][wp] = ffma2(t1, a[1][wp], o1[1][k][wp]);
                }
            }
        }
    }

    // ======== phase C: W1: out0[w] += (v1[u].v2[v]) * (INV_SQRT3*W1)[u,v,w] ========
#pragma unroll
    for (int vh = 0; vh < 2; vh++) {
        float v2l[2][4][3];
#pragma unroll
        for (int vl = 0; vl < 4; vl++)
#pragma unroll
            for (int k = 0; k < 3; k++) {
                v2l[0][vl][k] = S0[40 + (vh * 4 + vl) * 3 + k];
                v2l[1][vl][k] = S1[40 + (vh * 4 + vl) * 3 + k];
            }
#pragma unroll
        for (int u = 0; u < 8; u++) {
            float v1u[2][3];
#pragma unroll
            for (int k = 0; k < 3; k++) {
                v1u[0][k] = S0[8 + u * 3 + k];
                v1u[1][k] = S1[8 + u * 3 + k];
            }
#pragma unroll
            for (int vl = 0; vl < 4; vl++) {
                const float* wp = &ws[512 + u * 64 + (vh * 4 + vl) * 8];
                ulonglong2 q0 = *(const ulonglong2*)wp;
                ulonglong2 q1 = *(const ulonglong2*)(wp + 4);
#pragma unroll
                for (int je = 0; je < 2; je++) {
                    float p = v1u[je][0] * v2l[je][vl][0];
                    p = fmaf(v1u[je][1], v2l[je][vl][1], p);
                    p = fmaf(v1u[je][2], v2l[je][vl][2], p);
                    u64 pd = dup2(p);
                    o0[je][0] = ffma2(pd, q0.x, o0[je][0]);
                    o0[je][1] = ffma2(pd, q0.y, o0[je][1]);
                    o0[je][2] = ffma2(pd, q1.x, o0[je][2]);
                    o0[je][3] = ffma2(pd, q1.y, o0[je][3]);
                }
            }
        }
    }

    // ======== write outputs into own staging rows, then coalesced drain ========
#pragma unroll
    for (int je = 0; je < 2; je++) {
        float r[32];
        upk2(o0[je][0], r[0], r[1]); upk2(o0[je][1], r[2], r[3]);
        upk2(o0[je][2], r[4], r[5]); upk2(o0[je][3], r[6], r[7]);
#pragma unroll
        for (int k = 0; k < 3; k++)
#pragma unroll
            for (int wp = 0; wp < 4; wp++) {
                float lo, hi;
                upk2(o1[je][k][wp], lo, hi);
                r[8 + (2 * wp)     * 3 + k] = lo;
                r[8 + (2 * wp + 1) * 3 + k] = hi;
            }
        float* P = st + (tid + je * 128) * EPITCH;
#pragma unroll
        for (int f = 0; f < 32; f++) P[f] = r[f];
    }
    __syncthreads();
    {
        float4* go = (float4*)(out + eBase * 32);
#pragma unroll
        for (int c = 0; c < 16; c++) {
            int lin = tid + c * 128;
            int e = lin >> 3, j = (lin & 7) << 2;
            const float* p = st + e * EPITCH + j;
            go[lin] = make_float4(p[0], p[1], p[2], p[3]);
        }
    }
}

extern "C" void kernel_launch(void* const* d_in, const int* in_sizes, int n_in,
                              void* d_out, int out_size)
{
    const float* x1 = (const float*)d_in[0];
    const float* x2 = (const float*)d_in[1];
    const float* wt = (const float*)d_in[2];
    float* out = (float*)d_out;

    int nelem  = out_size / 32;                     // 2^20
    int blocks = nelem / 256;                       // 256 elements per block
    size_t smem = (2048 + 256 * EPITCH) * sizeof(float);  // 74752 B

    static bool attr_set = false;
    if (!attr_set) {
        cudaFuncSetAttribute(fctp_kernel,
                             cudaFuncAttributeMaxDynamicSharedMemorySize,
                             (int)smem);
        attr_set = true;
    }
    fctp_kernel<<<blocks, 128, smem>>>(x1, x2, wt, out);
}

// round 5
// speedup vs baseline: 1.4572x; 1.0092x over previous
#include <cuda_runtime.h>

// FullyConnectedTensorProduct: B=2^20, MUL=8, DIM=32, 4 paths of 8x8x8.
// R5: E=1 element/thread, 128-thread blocks, smem down to 41.5KB ->
// 5 blocks/SM = 20 warps (occupancy was the R4 limiter). Weights in smem
// (LDS.128 broadcast), inputs/outputs transpose-staged through stride-65
// padded smem (coalesced gmem, conflict-free LDS/STS). fma.rn.f32x2 packs
// adjacent w. ALPHA folded into x1 staging, INV_SQRT3 into path-1 weights.

typedef unsigned long long u64;

#define ALPHA_F     0.08838834764831845f   /* 1/sqrt(128) */
#define INV_SQRT3_F 0.5773502691896258f
#define EPITCH 65                          /* floats per element row in staging */

static __device__ __forceinline__ u64 pk2(float lo, float hi) {
    u64 r;
    asm("mov.b64 %0, {%1, %2};"
        : "=l"(r) : "r"(__float_as_uint(lo)), "r"(__float_as_uint(hi)));
    return r;
}
static __device__ __forceinline__ u64 dup2(float x) { return pk2(x, x); }
static __device__ __forceinline__ void upk2(u64 v, float& lo, float& hi) {
    unsigned l_, h_;
    asm("mov.b64 {%0, %1}, %2;" : "=r"(l_), "=r"(h_) : "l"(v));
    lo = __uint_as_float(l_);
    hi = __uint_as_float(h_);
}
static __device__ __forceinline__ u64 ffma2(u64 a, u64 b, u64 c) {
    u64 d;
    asm("fma.rn.f32x2 %0, %1, %2, %3;" : "=l"(d) : "l"(a), "l"(b), "l"(c));
    return d;
}

// a[0..3] += s * W[0..7]  (8 consecutive weights = 4 packed pairs)
static __device__ __forceinline__ void wacc1(const float* wp, u64 s, u64 a[4]) {
    ulonglong2 q0 = *(const ulonglong2*)wp;
    ulonglong2 q1 = *(const ulonglong2*)(wp + 4);
    a[0] = ffma2(s, q0.x, a[0]);
    a[1] = ffma2(s, q0.y, a[1]);
    a[2] = ffma2(s, q1.x, a[2]);
    a[3] = ffma2(s, q1.y, a[3]);
}

__global__ __launch_bounds__(128, 5)
void fctp_kernel(const float* __restrict__ x1,
                 const float* __restrict__ x2,
                 const float* __restrict__ wt,
                 float* __restrict__ out)
{
    extern __shared__ __align__(16) float smem[];
    float* ws = smem;              // 2048 floats: weights (path1 * INV_SQRT3)
    float* st = smem + 2048;       // 128 * EPITCH: per-element staging

    const int tid = threadIdx.x;
    const size_t eBase = (size_t)blockIdx.x * 128;

    // ---- stage weights (INV_SQRT3 folded into path 1) ----
#pragma unroll
    for (int c = 0; c < 16; c++) {
        int i = tid + c * 128;
        float s = ((i >> 9) == 1) ? INV_SQRT3_F : 1.0f;
        ws[i] = __ldg(wt + i) * s;
    }

    // ---- stage inputs: x1*ALPHA at [e*65 + 0..31], x2 at [e*65 + 32..63] ----
    {
        const float4* g1 = (const float4*)(x1 + eBase * 32);
        const float4* g2 = (const float4*)(x2 + eBase * 32);
#pragma unroll
        for (int c = 0; c < 8; c++) {
            int lin = tid + c * 128;          // float4 index in [0,1024)
            int e = lin >> 3, j = (lin & 7) << 2;
            float4 a = g1[lin];
            float* p = st + e * EPITCH + j;
            p[0] = a.x * ALPHA_F; p[1] = a.y * ALPHA_F;
            p[2] = a.z * ALPHA_F; p[3] = a.w * ALPHA_F;
            float4 b = g2[lin];
            float* q = st + e * EPITCH + 32 + j;
            q[0] = b.x; q[1] = b.y; q[2] = b.z; q[3] = b.w;
        }
    }
    __syncthreads();

    const float* S = st + tid * EPITCH;

    u64 o0[4] = {};
    u64 o1[3][4] = {};

    // ======== phase A: W0 + W2 (both contract u against s1) ========
    {
        u64 s1d[8];
#pragma unroll
        for (int u = 0; u < 8; u++) s1d[u] = dup2(S[u]);

        // W0: out0[w] += s2[v] * (sum_u s1[u] * W0[u,v,w])
#pragma unroll
        for (int v = 0; v < 8; v++) {
            u64 a[4] = {};
#pragma unroll
            for (int u = 0; u < 8; u++)
                wacc1(&ws[u * 64 + v * 8], s1d[u], a);
            u64 t = dup2(S[32 + v]);
#pragma unroll
            for (int i = 0; i < 4; i++) o0[i] = ffma2(t, a[i], o0[i]);
        }

        // W2: out1[w,k] += v2[v,k] * (sum_u s1[u] * W2[u,v,w])
#pragma unroll
        for (int v = 0; v < 8; v++) {
            u64 a[4] = {};
#pragma unroll
            for (int u = 0; u < 8; u++)
                wacc1(&ws[1024 + u * 64 + v * 8], s1d[u], a);
#pragma unroll
            for (int k = 0; k < 3; k++) {
                u64 t = dup2(S[40 + v * 3 + k]);
#pragma unroll
                for (int wp = 0; wp < 4; wp++)
                    o1[k][wp] = ffma2(t, a[wp], o1[k][wp]);
            }
        }
    }

    // ======== phase B: W3 (contract v against s2) ========
    {
        u64 s2d[8];
#pragma unroll
        for (int v = 0; v < 8; v++) s2d[v] = dup2(S[32 + v]);
#pragma unroll
        for (int u = 0; u < 8; u++) {
            u64 a[4] = {};
#pragma unroll
            for (int v = 0; v < 8; v++)
                wacc1(&ws[1536 + u * 64 + v * 8], s2d[v], a);
#pragma unroll
            for (int k = 0; k < 3; k++) {
                u64 t = dup2(S[8 + u * 3 + k]);
#pragma unroll
                for (int wp = 0; wp < 4; wp++)
                    o1[k][wp] = ffma2(t, a[wp], o1[k][wp]);
            }
        }
    }

    // ======== phase C: W1: out0[w] += (v1[u].v2[v]) * (INV_SQRT3*W1)[u,v,w] ========
    {
        float v2l[24];
#pragma unroll
        for (int i = 0; i < 24; i++) v2l[i] = S[40 + i];
#pragma unroll
        for (int u = 0; u < 8; u++) {
            float a0 = S[8 + u * 3 + 0];
            float a1 = S[8 + u * 3 + 1];
            float a2 = S[8 + u * 3 + 2];
#pragma unroll
            for (int v = 0; v < 8; v++) {
                float p = a0 * v2l[v * 3 + 0];
                p = fmaf(a1, v2l[v * 3 + 1], p);
                p = fmaf(a2, v2l[v * 3 + 2], p);
                u64 pd = dup2(p);
                const float* wp = &ws[512 + u * 64 + v * 8];
                ulonglong2 q0 = *(const ulonglong2*)wp;
                ulonglong2 q1 = *(const ulonglong2*)(wp + 4);
                o0[0] = ffma2(pd, q0.x, o0[0]);
                o0[1] = ffma2(pd, q0.y, o0[1]);
                o0[2] = ffma2(pd, q1.x, o0[2]);
                o0[3] = ffma2(pd, q1.y, o0[3]);
            }
        }
    }

    // ======== write outputs into own staging row, then coalesced drain ========
    __syncthreads();   // everyone done reading st before overwrite
    {
        float r[32];
        upk2(o0[0], r[0], r[1]); upk2(o0[1], r[2], r[3]);
        upk2(o0[2], r[4], r[5]); upk2(o0[3], r[6], r[7]);
#pragma unroll
        for (int k = 0; k < 3; k++)
#pragma unroll
            for (int wp = 0; wp < 4; wp++) {
                float lo, hi;
                upk2(o1[k][wp], lo, hi);
                r[8 + (2 * wp)     * 3 + k] = lo;
                r[8 + (2 * wp + 1) * 3 + k] = hi;
            }
        float* P = st + tid * EPITCH;
#pragma unroll
        for (int f = 0; f < 32; f++) P[f] = r[f];
    }
    __syncthreads();
    {
        float4* go = (float4*)(out + eBase * 32);
#pragma unroll
        for (int c = 0; c < 8; c++) {
            int lin = tid + c * 128;
            int e = lin >> 3, j = (lin & 7) << 2;
            const float* p = st + e * EPITCH + j;
            go[lin] = make_float4(p[0], p[1], p[2], p[3]);
        }
    }
}

extern "C" void kernel_launch(void* const* d_in, const int* in_sizes, int n_in,
                              void* d_out, int out_size)
{
    const float* x1 = (const float*)d_in[0];
    const float* x2 = (const float*)d_in[1];
    const float* wt = (const float*)d_in[2];
    float* out = (float*)d_out;

    int nelem  = out_size / 32;                     // 2^20
    int blocks = nelem / 128;                       // 128 elements per block
    size_t smem = (2048 + 128 * EPITCH) * sizeof(float);  // 41472 B

    static bool attr_set = false;
    if (!attr_set) {
        cudaFuncSetAttribute(fctp_kernel,
                             cudaFuncAttributeMaxDynamicSharedMemorySize,
                             (int)smem);
        attr_set = true;
    }
    fctp_kernel<<<blocks, 128, smem>>>(x1, x2, wt, out);
}

// round 6
// speedup vs baseline: 2.2858x; 1.5686x over previous
#include <cuda_runtime.h>

// FullyConnectedTensorProduct: B=2^20, MUL=8, DIM=32, 4 paths of 8x8x8.
// R6: weights moved to __constant__ memory (LDC broadcasts to all lanes via
// the const port -> zero L1-crossbar traffic, which bound R5 at L1=82%).
// E=1 element/thread, inputs/outputs transpose-staged through stride-65
// padded smem (coalesced gmem, conflict-free LDS/STS). fma.rn.f32x2 packs
// adjacent w. ALPHA folded into x1 at staging; INV_SQRT3 folded into v1
// reads in the W1 phase.

typedef unsigned long long u64;

#define ALPHA_F     0.08838834764831845f   /* 1/sqrt(128) */
#define INV_SQRT3_F 0.5773502691896258f
#define EPITCH 65                          /* floats per element row in staging */

__constant__ __align__(16) float cw[2048];  // raw weights (8 KB)

static __device__ __forceinline__ u64 pk2(float lo, float hi) {
    u64 r;
    asm("mov.b64 %0, {%1, %2};"
        : "=l"(r) : "r"(__float_as_uint(lo)), "r"(__float_as_uint(hi)));
    return r;
}
static __device__ __forceinline__ u64 dup2(float x) { return pk2(x, x); }
static __device__ __forceinline__ void upk2(u64 v, float& lo, float& hi) {
    unsigned l_, h_;
    asm("mov.b64 {%0, %1}, %2;" : "=r"(l_), "=r"(h_) : "l"(v));
    lo = __uint_as_float(l_);
    hi = __uint_as_float(h_);
}
static __device__ __forceinline__ u64 ffma2(u64 a, u64 b, u64 c) {
    u64 d;
    asm("fma.rn.f32x2 %0, %1, %2, %3;" : "=l"(d) : "l"(a), "l"(b), "l"(c));
    return d;
}

// a[0..3] += s * cw[off..off+7]  (8 consecutive weights = 4 packed pairs)
static __device__ __forceinline__ void wacc1(int off, u64 s, u64 a[4]) {
    ulonglong2 q0 = *(const ulonglong2*)(cw + off);
    ulonglong2 q1 = *(const ulonglong2*)(cw + off + 4);
    a[0] = ffma2(s, q0.x, a[0]);
    a[1] = ffma2(s, q0.y, a[1]);
    a[2] = ffma2(s, q1.x, a[2]);
    a[3] = ffma2(s, q1.y, a[3]);
}

__global__ __launch_bounds__(128, 5)
void fctp_kernel(const float* __restrict__ x1,
                 const float* __restrict__ x2,
                 float* __restrict__ out)
{
    extern __shared__ __align__(16) float st[];   // 128 * EPITCH staging

    const int tid = threadIdx.x;
    const size_t eBase = (size_t)blockIdx.x * 128;

    // ---- stage inputs: x1*ALPHA at [e*65 + 0..31], x2 at [e*65 + 32..63] ----
    {
        const float4* g1 = (const float4*)(x1 + eBase * 32);
        const float4* g2 = (const float4*)(x2 + eBase * 32);
#pragma unroll
        for (int c = 0; c < 8; c++) {
            int lin = tid + c * 128;          // float4 index in [0,1024)
            int e = lin >> 3, j = (lin & 7) << 2;
            float4 a = g1[lin];
            float* p = st + e * EPITCH + j;
            p[0] = a.x * ALPHA_F; p[1] = a.y * ALPHA_F;
            p[2] = a.z * ALPHA_F; p[3] = a.w * ALPHA_F;
            float4 b = g2[lin];
            float* q = st + e * EPITCH + 32 + j;
            q[0] = b.x; q[1] = b.y; q[2] = b.z; q[3] = b.w;
        }
    }
    __syncthreads();

    const float* S = st + tid * EPITCH;

    u64 o0[4] = {};
    u64 o1[3][4] = {};

    // ======== phase A: W0 + W2 (both contract u against s1) ========
    {
        u64 s1d[8];
#pragma unroll
        for (int u = 0; u < 8; u++) s1d[u] = dup2(S[u]);

        // W0: out0[w] += s2[v] * (sum_u s1[u] * W0[u,v,w])
#pragma unroll
        for (int v = 0; v < 8; v++) {
            u64 a[4] = {};
#pragma unroll
            for (int u = 0; u < 8; u++)
                wacc1(u * 64 + v * 8, s1d[u], a);
            u64 t = dup2(S[32 + v]);
#pragma unroll
            for (int i = 0; i < 4; i++) o0[i] = ffma2(t, a[i], o0[i]);
        }

        // W2: out1[w,k] += v2[v,k] * (sum_u s1[u] * W2[u,v,w])
#pragma unroll
        for (int v = 0; v < 8; v++) {
            u64 a[4] = {};
#pragma unroll
            for (int u = 0; u < 8; u++)
                wacc1(1024 + u * 64 + v * 8, s1d[u], a);
#pragma unroll
            for (int k = 0; k < 3; k++) {
                u64 t = dup2(S[40 + v * 3 + k]);
#pragma unroll
                for (int wp = 0; wp < 4; wp++)
                    o1[k][wp] = ffma2(t, a[wp], o1[k][wp]);
            }
        }
    }

    // ======== phase B: W3 (contract v against s2) ========
    {
        u64 s2d[8];
#pragma unroll
        for (int v = 0; v < 8; v++) s2d[v] = dup2(S[32 + v]);
#pragma unroll
        for (int u = 0; u < 8; u++) {
            u64 a[4] = {};
#pragma unroll
            for (int v = 0; v < 8; v++)
                wacc1(1536 + u * 64 + v * 8, s2d[v], a);
#pragma unroll
            for (int k = 0; k < 3; k++) {
                u64 t = dup2(S[8 + u * 3 + k]);
#pragma unroll
                for (int wp = 0; wp < 4; wp++)
                    o1[k][wp] = ffma2(t, a[wp], o1[k][wp]);
            }
        }
    }

    // ======== phase C: W1: out0[w] += INV_SQRT3*(v1[u].v2[v]) * W1[u,v,w] ========
    {
        float v2l[24];
#pragma unroll
        for (int i = 0; i < 24; i++) v2l[i] = S[40 + i];
#pragma unroll
        for (int u = 0; u < 8; u++) {
            float a0 = S[8 + u * 3 + 0] * INV_SQRT3_F;
            float a1 = S[8 + u * 3 + 1] * INV_SQRT3_F;
            float a2 = S[8 + u * 3 + 2] * INV_SQRT3_F;
#pragma unroll
            for (int v = 0; v < 8; v++) {
                float p = a0 * v2l[v * 3 + 0];
                p = fmaf(a1, v2l[v * 3 + 1], p);
                p = fmaf(a2, v2l[v * 3 + 2], p);
                u64 pd = dup2(p);
                const int off = 512 + u * 64 + v * 8;
                ulonglong2 q0 = *(const ulonglong2*)(cw + off);
                ulonglong2 q1 = *(const ulonglong2*)(cw + off + 4);
                o0[0] = ffma2(pd, q0.x, o0[0]);
                o0[1] = ffma2(pd, q0.y, o0[1]);
                o0[2] = ffma2(pd, q1.x, o0[2]);
                o0[3] = ffma2(pd, q1.y, o0[3]);
            }
        }
    }

    // ======== write outputs into own staging row, then coalesced drain ========
    __syncthreads();   // everyone done reading st before overwrite
    {
        float r[32];
        upk2(o0[0], r[0], r[1]); upk2(o0[1], r[2], r[3]);
        upk2(o0[2], r[4], r[5]); upk2(o0[3], r[6], r[7]);
#pragma unroll
        for (int k = 0; k < 3; k++)
#pragma unroll
            for (int wp = 0; wp < 4; wp++) {
                float lo, hi;
                upk2(o1[k][wp], lo, hi);
                r[8 + (2 * wp)     * 3 + k] = lo;
                r[8 + (2 * wp + 1) * 3 + k] = hi;
            }
        float* P = st + tid * EPITCH;
#pragma unroll
        for (int f = 0; f < 32; f++) P[f] = r[f];
    }
    __syncthreads();
    {
        float4* go = (float4*)(out + eBase * 32);
#pragma unroll
        for (int c = 0; c < 8; c++) {
            int lin = tid + c * 128;
            int e = lin >> 3, j = (lin & 7) << 2;
            const float* p = st + e * EPITCH + j;
            go[lin] = make_float4(p[0], p[1], p[2], p[3]);
        }
    }
}

extern "C" void kernel_launch(void* const* d_in, const int* in_sizes, int n_in,
                              void* d_out, int out_size)
{
    const float* x1 = (const float*)d_in[0];
    const float* x2 = (const float*)d_in[1];
    const float* wt = (const float*)d_in[2];
    float* out = (float*)d_out;

    // Copy raw weights into constant memory (D2D async: graph-capturable).
    cudaMemcpyToSymbolAsync(cw, wt, 2048 * sizeof(float), 0,
                            cudaMemcpyDeviceToDevice, 0);

    int nelem  = out_size / 32;                     // 2^20
    int blocks = nelem / 128;                       // 128 elements per block
    size_t smem = (128 * EPITCH) * sizeof(float);   // 33280 B

    static bool attr_set = false;
    if (!attr_set) {
        cudaFuncSetAttribute(fctp_kernel,
                             cudaFuncAttributeMaxDynamicSharedMemorySize,
                             (int)smem);
        attr_set = true;
    }
    fctp_kernel<<<blocks, 128, smem>>>(x1, x2, out);
}